// round 1
// baseline (speedup 1.0000x reference)
#include <cuda_runtime.h>

#define NI 40000
#define NU 30000
#define NF 30000
#define NN 100000
#define EE 1200000
#define ET (EE + NN)
#define NEG 0.2f

// ---- output layout (tuple order, flattened) ----
static const size_t OFF_ITEM  = 0;
static const size_t OFF_USER  = OFF_ITEM + (size_t)NI * 64;
static const size_t OFF_FET   = OFF_USER + (size_t)NU * 64;
static const size_t OFF_FINAL = OFF_FET  + (size_t)NF * 64;
static const size_t OFF_A1    = OFF_FINAL + (size_t)NN * 64;
static const size_t OFF_A2    = OFF_A1 + (size_t)ET * 2;
static const size_t OFF_A3    = OFF_A2 + (size_t)ET * 2;

// ---- scratch (device globals; no allocation allowed) ----
__device__ float g_xw[(size_t)NN * 128];
__device__ float g_x1[(size_t)NN * 128];
__device__ float g_x2[(size_t)NN * 128];
__device__ float g_x3[(size_t)NN * 64];
__device__ float g_as[(size_t)NN * 2];
__device__ float g_ad[(size_t)NN * 2];
__device__ int   g_cnt[NN];
__device__ int   g_off[NN + 1];
__device__ int   g_cur[NN];
__device__ int   g_eid[ET];
__device__ int   g_bsum[128];

__device__ __forceinline__ int edge_src(const int* ei, int e) {
    return (e < EE) ? ei[e] : (e - EE);
}
__device__ __forceinline__ int edge_dst(const int* ei, int e) {
    return (e < EE) ? ei[EE + e] : (e - EE);
}

// ================= CSR build =================
__global__ void k_zero_cnt() {
    int i = blockIdx.x * blockDim.x + threadIdx.x;
    if (i < NN) g_cnt[i] = 0;
}

__global__ void k_count(const int* __restrict__ ei) {
    for (int e = blockIdx.x * blockDim.x + threadIdx.x; e < ET;
         e += gridDim.x * blockDim.x) {
        atomicAdd(&g_cnt[edge_dst(ei, e)], 1);
    }
}

__global__ void k_scan1() {
    __shared__ int sh[1024];
    int i = blockIdx.x * 1024 + threadIdx.x;
    int v = (i < NN) ? g_cnt[i] : 0;
    sh[threadIdx.x] = v;
    __syncthreads();
    for (int o = 1; o < 1024; o <<= 1) {
        int t = (threadIdx.x >= (unsigned)o) ? sh[threadIdx.x - o] : 0;
        __syncthreads();
        sh[threadIdx.x] += t;
        __syncthreads();
    }
    if (i < NN) g_off[i + 1] = sh[threadIdx.x];
    if (threadIdx.x == 1023) g_bsum[blockIdx.x] = sh[1023];
}

__global__ void k_scan2(int nb) {
    __shared__ int sh[128];
    int v = ((int)threadIdx.x < nb) ? g_bsum[threadIdx.x] : 0;
    sh[threadIdx.x] = v;
    __syncthreads();
    for (int o = 1; o < 128; o <<= 1) {
        int t = (threadIdx.x >= (unsigned)o) ? sh[threadIdx.x - o] : 0;
        __syncthreads();
        sh[threadIdx.x] += t;
        __syncthreads();
    }
    if ((int)threadIdx.x < nb) g_bsum[threadIdx.x] = sh[threadIdx.x] - v;
}

__global__ void k_scan3() {
    int i = blockIdx.x * 1024 + threadIdx.x;
    if (i < NN) g_off[i + 1] += g_bsum[blockIdx.x];
    if (i == 0) g_off[0] = 0;
}

__global__ void k_cursor() {
    int i = blockIdx.x * blockDim.x + threadIdx.x;
    if (i < NN) g_cur[i] = g_off[i];
}

__global__ void k_scatter(const int* __restrict__ ei) {
    for (int e = blockIdx.x * blockDim.x + threadIdx.x; e < ET;
         e += gridDim.x * blockDim.x) {
        int d = edge_dst(ei, e);
        int pos = atomicAdd(&g_cur[d], 1);
        g_eid[pos] = e;
    }
}

// ================= GEMM: xw = act(x) @ W =================
// AMODE 0: x = concat(emb_item, emb_user, emb_fet)  (K=64)
// AMODE 1: x = relu(g_x1)  (K=128)
// AMODE 2: x = relu(g_x2)  (K=128)
template <int KD, int NC, int AMODE>
__global__ void k_gemm(const float* __restrict__ Ei, const float* __restrict__ Eu,
                       const float* __restrict__ Ef, const float* __restrict__ W) {
    constexpr int BM = 128, BK = 16;
    constexpr int TM = 8, TN = NC / 16;
    __shared__ float As[BK][BM];
    __shared__ float Bs[BK][NC];

    const int row0 = blockIdx.x * BM;
    const int tx = threadIdx.x % 16;
    const int ty = threadIdx.x / 16;

    float acc[TM][TN];
#pragma unroll
    for (int m = 0; m < TM; m++)
#pragma unroll
        for (int n = 0; n < TN; n++) acc[m][n] = 0.f;

    for (int k0 = 0; k0 < KD; k0 += BK) {
        // ---- load A tile (BM x BK), transposed into As[k][m] ----
#pragma unroll
        for (int l = 0; l < 2; l++) {
            int idx = threadIdx.x + l * 256;  // 512 float4 slots
            int m = idx >> 2;
            int kq = (idx & 3) * 4;
            int row = row0 + m;
            float4 v = make_float4(0.f, 0.f, 0.f, 0.f);
            if (row < NN) {
                const float* ap;
                if (AMODE == 0) {
                    ap = (row < NI) ? (Ei + (size_t)row * 64)
                        : (row < NI + NU) ? (Eu + (size_t)(row - NI) * 64)
                                          : (Ef + (size_t)(row - NI - NU) * 64);
                } else if (AMODE == 1) {
                    ap = g_x1 + (size_t)row * KD;
                } else {
                    ap = g_x2 + (size_t)row * KD;
                }
                v = *(const float4*)(ap + k0 + kq);
                if (AMODE != 0) {
                    v.x = fmaxf(v.x, 0.f); v.y = fmaxf(v.y, 0.f);
                    v.z = fmaxf(v.z, 0.f); v.w = fmaxf(v.w, 0.f);
                }
            }
            As[kq + 0][m] = v.x; As[kq + 1][m] = v.y;
            As[kq + 2][m] = v.z; As[kq + 3][m] = v.w;
        }
        // ---- load B tile (BK x NC) ----
#pragma unroll
        for (int l = 0; l < (BK * NC) / 1024; l++) {
            int idx = threadIdx.x + l * 256;  // float4 slots
            int kk = idx / (NC / 4);
            int nq = (idx % (NC / 4)) * 4;
            float4 v = *(const float4*)(W + (size_t)(k0 + kk) * NC + nq);
            *(float4*)&Bs[kk][nq] = v;
        }
        __syncthreads();

#pragma unroll
        for (int kk = 0; kk < BK; kk++) {
            float ra[TM], rb[TN];
#pragma unroll
            for (int m = 0; m < TM; m += 4) {
                float4 t = *(const float4*)&As[kk][ty * TM + m];
                ra[m] = t.x; ra[m + 1] = t.y; ra[m + 2] = t.z; ra[m + 3] = t.w;
            }
#pragma unroll
            for (int n = 0; n < TN; n += 4) {
                float4 t = *(const float4*)&Bs[kk][tx * TN + n];
                rb[n] = t.x; rb[n + 1] = t.y; rb[n + 2] = t.z; rb[n + 3] = t.w;
            }
#pragma unroll
            for (int m = 0; m < TM; m++)
#pragma unroll
                for (int n = 0; n < TN; n++) acc[m][n] += ra[m] * rb[n];
        }
        __syncthreads();
    }

    // ---- store ----
#pragma unroll
    for (int m = 0; m < TM; m++) {
        int row = row0 + ty * TM + m;
        if (row < NN) {
            float* op = g_xw + (size_t)row * NC + tx * TN;
#pragma unroll
            for (int n = 0; n < TN; n += 4) {
                *(float4*)&op[n] = make_float4(acc[m][n], acc[m][n + 1],
                                               acc[m][n + 2], acc[m][n + 3]);
            }
        }
    }
}

// ================= attention scores a_src/a_dst =================
__global__ void k_att2(const float* __restrict__ att_s, const float* __restrict__ att_d) {
    int gw = (blockIdx.x * blockDim.x + threadIdx.x) >> 5;
    int lane = threadIdx.x & 31;
    if (gw >= NN) return;
    float4 v = *(const float4*)&g_xw[(size_t)gw * 128 + lane * 4];
    float4 s = *(const float4*)&att_s[lane * 4];
    float4 d = *(const float4*)&att_d[lane * 4];
    float ps = v.x * s.x + v.y * s.y + v.z * s.z + v.w * s.w;
    float pd = v.x * d.x + v.y * d.y + v.z * d.z + v.w * d.w;
#pragma unroll
    for (int o = 8; o > 0; o >>= 1) {
        ps += __shfl_xor_sync(0xffffffffu, ps, o, 16);
        pd += __shfl_xor_sync(0xffffffffu, pd, o, 16);
    }
    if ((lane & 15) == 0) {
        g_as[gw * 2 + (lane >> 4)] = ps;
        g_ad[gw * 2 + (lane >> 4)] = pd;
    }
}

__global__ void k_att1(const float* __restrict__ att_s, const float* __restrict__ att_d) {
    int gw = (blockIdx.x * blockDim.x + threadIdx.x) >> 5;
    int lane = threadIdx.x & 31;
    if (gw >= NN) return;
    float2 v = *(const float2*)&g_xw[(size_t)gw * 64 + lane * 2];
    float2 s = *(const float2*)&att_s[lane * 2];
    float2 d = *(const float2*)&att_d[lane * 2];
    float ps = v.x * s.x + v.y * s.y;
    float pd = v.x * d.x + v.y * d.y;
#pragma unroll
    for (int o = 16; o > 0; o >>= 1) {
        ps += __shfl_xor_sync(0xffffffffu, ps, o);
        pd += __shfl_xor_sync(0xffffffffu, pd, o);
    }
    if (lane == 0) { g_as[gw] = ps; g_ad[gw] = pd; }
}

__device__ __forceinline__ float lrelu(float x) { return x > 0.f ? x : NEG * x; }

// ================= per-node softmax + aggregation =================
// H heads (1 or 2), SEL: 1->g_x1, 2->g_x2, 3->g_x3
template <int H, int SEL>
__global__ void k_agg(const int* __restrict__ ei, const float* __restrict__ bias,
                      float* __restrict__ alpha_out) {
    int node = (blockIdx.x * blockDim.x + threadIdx.x) >> 5;
    int lane = threadIdx.x & 31;
    if (node >= NN) return;
    const int s0 = g_off[node];
    const int s1 = g_off[node + 1];
    const float ad0 = g_ad[node * H + 0];
    const float ad1 = (H == 2) ? g_ad[node * H + 1] : 0.f;

    // pass 1: segment max
    float m0 = -INFINITY, m1 = -INFINITY;
    for (int j = s0 + lane; j < s1; j += 32) {
        int e = g_eid[j];
        int src = edge_src(ei, e);
        m0 = fmaxf(m0, lrelu(g_as[src * H + 0] + ad0));
        if (H == 2) m1 = fmaxf(m1, lrelu(g_as[src * H + 1] + ad1));
    }
#pragma unroll
    for (int o = 16; o > 0; o >>= 1) {
        m0 = fmaxf(m0, __shfl_xor_sync(0xffffffffu, m0, o));
        if (H == 2) m1 = fmaxf(m1, __shfl_xor_sync(0xffffffffu, m1, o));
    }

    // pass 2: segment sum of exp
    float sum0 = 0.f, sum1 = 0.f;
    for (int j = s0 + lane; j < s1; j += 32) {
        int e = g_eid[j];
        int src = edge_src(ei, e);
        sum0 += expf(lrelu(g_as[src * H + 0] + ad0) - m0);
        if (H == 2) sum1 += expf(lrelu(g_as[src * H + 1] + ad1) - m1);
    }
#pragma unroll
    for (int o = 16; o > 0; o >>= 1) {
        sum0 += __shfl_xor_sync(0xffffffffu, sum0, o);
        if (H == 2) sum1 += __shfl_xor_sync(0xffffffffu, sum1, o);
    }
    const float inv0 = 1.f / (sum0 + 1e-16f);
    const float inv1 = (H == 2) ? 1.f / (sum1 + 1e-16f) : 0.f;

    // pass 3: weighted aggregation (warp-wide gather per edge)
    float acc0 = 0.f, acc1 = 0.f, acc2 = 0.f, acc3 = 0.f;
    for (int j = s0; j < s1; j++) {
        int e = g_eid[j];            // uniform broadcast load
        int src = edge_src(ei, e);   // uniform broadcast load
        float a0 = expf(lrelu(g_as[src * H + 0] + ad0) - m0) * inv0;
        float a1 = (H == 2) ? expf(lrelu(g_as[src * H + 1] + ad1) - m1) * inv1 : 0.f;
        if (lane == 0) {
            if (H == 2) *(float2*)&alpha_out[(size_t)e * 2] = make_float2(a0, a1);
            else alpha_out[e] = a0;
        }
        if (H == 2) {
            float4 v = *(const float4*)&g_xw[(size_t)src * 128 + lane * 4];
            float a = (lane < 16) ? a0 : a1;
            acc0 += a * v.x; acc1 += a * v.y; acc2 += a * v.z; acc3 += a * v.w;
        } else {
            float2 v = *(const float2*)&g_xw[(size_t)src * 64 + lane * 2];
            acc0 += a0 * v.x; acc1 += a0 * v.y;
        }
    }

    if (H == 2) {
        float4 b = *(const float4*)&bias[lane * 4];
        float* out = (SEL == 1) ? g_x1 : g_x2;
        *(float4*)&out[(size_t)node * 128 + lane * 4] =
            make_float4(acc0 + b.x, acc1 + b.y, acc2 + b.z, acc3 + b.w);
    } else {
        float2 b = *(const float2*)&bias[lane * 2];
        *(float2*)&g_x3[(size_t)node * 64 + lane * 2] =
            make_float2(acc0 + b.x, acc1 + b.y);
    }
}

// ================= final combine + output slices =================
__global__ void k_final(const float* __restrict__ Ei, const float* __restrict__ Eu,
                        const float* __restrict__ Ef, float* __restrict__ out) {
    int t = blockIdx.x * blockDim.x + threadIdx.x;
    if (t >= NN * 16) return;
    int n = t >> 4;
    int dq = (t & 15) * 4;
    const float* x0p = (n < NI) ? (Ei + (size_t)n * 64)
                     : (n < NI + NU) ? (Eu + (size_t)(n - NI) * 64)
                                     : (Ef + (size_t)(n - NI - NU) * 64);
    float4 x0 = *(const float4*)(x0p + dq);
    float4 a = *(const float4*)&g_x1[(size_t)n * 128 + dq];
    float4 b = *(const float4*)&g_x1[(size_t)n * 128 + 64 + dq];
    float4 c = *(const float4*)&g_x2[(size_t)n * 128 + dq];
    float4 d = *(const float4*)&g_x2[(size_t)n * 128 + 64 + dq];
    float4 x3 = *(const float4*)&g_x3[(size_t)n * 64 + dq];
    float4 f;
    f.x = (x0.x + 0.5f * (a.x + b.x) + 0.5f * (c.x + d.x) + x3.x) * 0.25f;
    f.y = (x0.y + 0.5f * (a.y + b.y) + 0.5f * (c.y + d.y) + x3.y) * 0.25f;
    f.z = (x0.z + 0.5f * (a.z + b.z) + 0.5f * (c.z + d.z) + x3.z) * 0.25f;
    f.w = (x0.w + 0.5f * (a.w + b.w) + 0.5f * (c.w + d.w) + x3.w) * 0.25f;
    *(float4*)&out[OFF_FINAL + (size_t)n * 64 + dq] = f;
    size_t so = (n < NI) ? (OFF_ITEM + (size_t)n * 64)
              : (n < NI + NU) ? (OFF_USER + (size_t)(n - NI) * 64)
                              : (OFF_FET + (size_t)(n - NI - NU) * 64);
    *(float4*)&out[so + dq] = f;
}

// ================= host launcher =================
extern "C" void kernel_launch(void* const* d_in, const int* in_sizes, int n_in,
                              void* d_out, int out_size) {
    const int*   ei   = (const int*)d_in[0];
    const float* embi = (const float*)d_in[1];
    const float* embu = (const float*)d_in[2];
    const float* embf = (const float*)d_in[3];
    const float* W1   = (const float*)d_in[4];
    const float* as1  = (const float*)d_in[5];
    const float* ad1  = (const float*)d_in[6];
    const float* b1   = (const float*)d_in[7];
    const float* W2   = (const float*)d_in[8];
    const float* as2  = (const float*)d_in[9];
    const float* ad2  = (const float*)d_in[10];
    const float* b2   = (const float*)d_in[11];
    const float* W3   = (const float*)d_in[12];
    const float* as3  = (const float*)d_in[13];
    const float* ad3  = (const float*)d_in[14];
    const float* b3   = (const float*)d_in[15];
    float* out = (float*)d_out;

    const int SCAN_BLOCKS = (NN + 1023) / 1024;  // 98

    // ---- CSR build (shared by all 3 layers) ----
    k_zero_cnt<<<(NN + 255) / 256, 256>>>();
    k_count<<<2048, 256>>>(ei);
    k_scan1<<<SCAN_BLOCKS, 1024>>>();
    k_scan2<<<1, 128>>>(SCAN_BLOCKS);
    k_scan3<<<SCAN_BLOCKS, 1024>>>();
    k_cursor<<<(NN + 255) / 256, 256>>>();
    k_scatter<<<2048, 256>>>(ei);

    const int GEMM_GRID = (NN + 127) / 128;  // 782
    const int WARP_GRID = (NN + 7) / 8;      // 12500 blocks of 8 warps

    // ---- layer 1 ----
    k_gemm<64, 128, 0><<<GEMM_GRID, 256>>>(embi, embu, embf, W1);
    k_att2<<<WARP_GRID, 256>>>(as1, ad1);
    k_agg<2, 1><<<WARP_GRID, 256>>>(ei, b1, out + OFF_A1);

    // ---- layer 2 ----
    k_gemm<128, 128, 1><<<GEMM_GRID, 256>>>(embi, embu, embf, W2);
    k_att2<<<WARP_GRID, 256>>>(as2, ad2);
    k_agg<2, 2><<<WARP_GRID, 256>>>(ei, b2, out + OFF_A2);

    // ---- layer 3 ----
    k_gemm<128, 64, 2><<<GEMM_GRID, 256>>>(embi, embu, embf, W3);
    k_att1<<<WARP_GRID, 256>>>(as3, ad3);
    k_agg<1, 3><<<WARP_GRID, 256>>>(ei, b3, out + OFF_A3);

    // ---- final combine ----
    k_final<<<(NN * 16 + 255) / 256, 256>>>(embi, embu, embf, out);
}

// round 2
// speedup vs baseline: 1.0210x; 1.0210x over previous
#include <cuda_runtime.h>
#include <cstdint>

#define NI 40000
#define NU 30000
#define NF 30000
#define NN 100000
#define EE 1200000
#define ET (EE + NN)
#define NEG 0.2f

// ---- output layout (tuple order, flattened) ----
static const size_t OFF_ITEM  = 0;
static const size_t OFF_USER  = OFF_ITEM + (size_t)NI * 64;
static const size_t OFF_FET   = OFF_USER + (size_t)NU * 64;
static const size_t OFF_FINAL = OFF_FET  + (size_t)NF * 64;
static const size_t OFF_A1    = OFF_FINAL + (size_t)NN * 64;
static const size_t OFF_A2    = OFF_A1 + (size_t)ET * 2;
static const size_t OFF_A3    = OFF_A2 + (size_t)ET * 2;

// ---- scratch (device globals; no allocation allowed) ----
__device__ float g_xw[(size_t)NN * 128];
__device__ float g_x1[(size_t)NN * 128];
__device__ float g_x2[(size_t)NN * 128];
__device__ float g_x3[(size_t)NN * 64];
__device__ float g_as[(size_t)NN * 2];
__device__ float g_ad[(size_t)NN * 2];
__device__ float g_esc[(size_t)ET * 2];   // CSR-ordered edge scores
__device__ int   g_cnt[NN];
__device__ int   g_off[NN + 1];
__device__ int   g_cur[NN];
__device__ int   g_eid[ET];
__device__ int   g_bsum[128];

__device__ __forceinline__ int edge_src(const int* ei, int e) {
    return (e < EE) ? ei[e] : (e - EE);
}
__device__ __forceinline__ int edge_dst(const int* ei, int e) {
    return (e < EE) ? ei[EE + e] : (e - EE);
}

__device__ __forceinline__ float lrelu(float x) { return x > 0.f ? x : NEG * x; }

// ---- packed f32x2 helpers ----
__device__ __forceinline__ unsigned long long pack2(float lo, float hi) {
    unsigned long long r;
    asm("mov.b64 %0, {%1, %2};" : "=l"(r) : "r"(__float_as_uint(lo)), "r"(__float_as_uint(hi)));
    return r;
}
__device__ __forceinline__ void unpack2(unsigned long long v, float& lo, float& hi) {
    unsigned int a, b;
    asm("mov.b64 {%0, %1}, %2;" : "=r"(a), "=r"(b) : "l"(v));
    lo = __uint_as_float(a); hi = __uint_as_float(b);
}
__device__ __forceinline__ void ffma2(unsigned long long& d, unsigned long long a,
                                      unsigned long long b) {
    asm("fma.rn.f32x2 %0, %1, %2, %0;" : "+l"(d) : "l"(a), "l"(b));
}

// ================= CSR build =================
__global__ void k_zero_cnt() {
    int i = blockIdx.x * blockDim.x + threadIdx.x;
    if (i < NN) g_cnt[i] = 0;
}

__global__ void k_count(const int* __restrict__ ei) {
    for (int e = blockIdx.x * blockDim.x + threadIdx.x; e < ET;
         e += gridDim.x * blockDim.x) {
        atomicAdd(&g_cnt[edge_dst(ei, e)], 1);
    }
}

__global__ void k_scan1() {
    __shared__ int sh[1024];
    int i = blockIdx.x * 1024 + threadIdx.x;
    int v = (i < NN) ? g_cnt[i] : 0;
    sh[threadIdx.x] = v;
    __syncthreads();
    for (int o = 1; o < 1024; o <<= 1) {
        int t = (threadIdx.x >= (unsigned)o) ? sh[threadIdx.x - o] : 0;
        __syncthreads();
        sh[threadIdx.x] += t;
        __syncthreads();
    }
    if (i < NN) g_off[i + 1] = sh[threadIdx.x];
    if (threadIdx.x == 1023) g_bsum[blockIdx.x] = sh[1023];
}

__global__ void k_scan2(int nb) {
    __shared__ int sh[128];
    int v = ((int)threadIdx.x < nb) ? g_bsum[threadIdx.x] : 0;
    sh[threadIdx.x] = v;
    __syncthreads();
    for (int o = 1; o < 128; o <<= 1) {
        int t = (threadIdx.x >= (unsigned)o) ? sh[threadIdx.x - o] : 0;
        __syncthreads();
        sh[threadIdx.x] += t;
        __syncthreads();
    }
    if ((int)threadIdx.x < nb) g_bsum[threadIdx.x] = sh[threadIdx.x] - v;
}

__global__ void k_scan3() {   // also initializes cursors
    int i = blockIdx.x * 1024 + threadIdx.x;
    if (i < NN) {
        int v = g_off[i + 1] + g_bsum[blockIdx.x];
        g_off[i + 1] = v;
        if (i + 1 < NN) g_cur[i + 1] = v;
    }
    if (i == 0) { g_off[0] = 0; g_cur[0] = 0; }
}

__global__ void k_scatter(const int* __restrict__ ei) {
    for (int e = blockIdx.x * blockDim.x + threadIdx.x; e < ET;
         e += gridDim.x * blockDim.x) {
        int d = edge_dst(ei, e);
        int pos = atomicAdd(&g_cur[d], 1);
        g_eid[pos] = e;
    }
}

// ================= GEMM: xw = act(x) @ W  (packed f32x2 FFMA) =================
// AMODE 0: x = concat(embeddings) (K=64); 1: relu(g_x1); 2: relu(g_x2)
template <int KD, int NC, int AMODE>
__global__ void k_gemm(const float* __restrict__ Ei, const float* __restrict__ Eu,
                       const float* __restrict__ Ef, const float* __restrict__ W) {
    constexpr int BM = 128, BK = 16;
    constexpr int TM = 8, TN = NC / 16;
    __shared__ float As[BK][BM];
    __shared__ float Bs[BK][NC];

    const int row0 = blockIdx.x * BM;
    const int tx = threadIdx.x % 16;
    const int ty = threadIdx.x / 16;

    unsigned long long acc2[TM][TN / 2];
#pragma unroll
    for (int m = 0; m < TM; m++)
#pragma unroll
        for (int n = 0; n < TN / 2; n++) acc2[m][n] = 0ull;

    for (int k0 = 0; k0 < KD; k0 += BK) {
        // ---- load A tile (BM x BK), transposed into As[k][m] ----
#pragma unroll
        for (int l = 0; l < 2; l++) {
            int idx = threadIdx.x + l * 256;  // 512 float4 slots
            int m = idx >> 2;
            int kq = (idx & 3) * 4;
            int row = row0 + m;
            float4 v = make_float4(0.f, 0.f, 0.f, 0.f);
            if (row < NN) {
                const float* ap;
                if (AMODE == 0) {
                    ap = (row < NI) ? (Ei + (size_t)row * 64)
                        : (row < NI + NU) ? (Eu + (size_t)(row - NI) * 64)
                                          : (Ef + (size_t)(row - NI - NU) * 64);
                } else if (AMODE == 1) {
                    ap = g_x1 + (size_t)row * KD;
                } else {
                    ap = g_x2 + (size_t)row * KD;
                }
                v = *(const float4*)(ap + k0 + kq);
                if (AMODE != 0) {
                    v.x = fmaxf(v.x, 0.f); v.y = fmaxf(v.y, 0.f);
                    v.z = fmaxf(v.z, 0.f); v.w = fmaxf(v.w, 0.f);
                }
            }
            As[kq + 0][m] = v.x; As[kq + 1][m] = v.y;
            As[kq + 2][m] = v.z; As[kq + 3][m] = v.w;
        }
        // ---- load B tile (BK x NC) ----
#pragma unroll
        for (int l = 0; l < (BK * NC) / 1024; l++) {
            int idx = threadIdx.x + l * 256;
            int kk = idx / (NC / 4);
            int nq = (idx % (NC / 4)) * 4;
            float4 v = *(const float4*)(W + (size_t)(k0 + kk) * NC + nq);
            *(float4*)&Bs[kk][nq] = v;
        }
        __syncthreads();

#pragma unroll
        for (int kk = 0; kk < BK; kk++) {
            float ra[TM];
            unsigned long long rb[TN / 2];
#pragma unroll
            for (int m = 0; m < TM; m += 4) {
                float4 t = *(const float4*)&As[kk][ty * TM + m];
                ra[m] = t.x; ra[m + 1] = t.y; ra[m + 2] = t.z; ra[m + 3] = t.w;
            }
#pragma unroll
            for (int n2 = 0; n2 < TN / 2; n2 += 2) {
                ulonglong2 t = *(const ulonglong2*)&Bs[kk][tx * TN + n2 * 2];
                rb[n2] = t.x; rb[n2 + 1] = t.y;
            }
#pragma unroll
            for (int m = 0; m < TM; m++) {
                unsigned long long a2 = pack2(ra[m], ra[m]);
#pragma unroll
                for (int n2 = 0; n2 < TN / 2; n2++) ffma2(acc2[m][n2], a2, rb[n2]);
            }
        }
        __syncthreads();
    }

    // ---- store ----
#pragma unroll
    for (int m = 0; m < TM; m++) {
        int row = row0 + ty * TM + m;
        if (row < NN) {
            float* op = g_xw + (size_t)row * NC + tx * TN;
#pragma unroll
            for (int n2 = 0; n2 < TN / 2; n2 += 2) {
                float4 o;
                unpack2(acc2[m][n2], o.x, o.y);
                unpack2(acc2[m][n2 + 1], o.z, o.w);
                *(float4*)&op[n2 * 2] = o;
            }
        }
    }
}

// ================= attention scores a_src/a_dst =================
__global__ void k_att2(const float* __restrict__ att_s, const float* __restrict__ att_d) {
    int gw = (blockIdx.x * blockDim.x + threadIdx.x) >> 5;
    int lane = threadIdx.x & 31;
    if (gw >= NN) return;
    float4 v = *(const float4*)&g_xw[(size_t)gw * 128 + lane * 4];
    float4 s = *(const float4*)&att_s[lane * 4];
    float4 d = *(const float4*)&att_d[lane * 4];
    float ps = v.x * s.x + v.y * s.y + v.z * s.z + v.w * s.w;
    float pd = v.x * d.x + v.y * d.y + v.z * d.z + v.w * d.w;
#pragma unroll
    for (int o = 8; o > 0; o >>= 1) {
        ps += __shfl_xor_sync(0xffffffffu, ps, o, 16);
        pd += __shfl_xor_sync(0xffffffffu, pd, o, 16);
    }
    if ((lane & 15) == 0) {
        g_as[gw * 2 + (lane >> 4)] = ps;
        g_ad[gw * 2 + (lane >> 4)] = pd;
    }
}

__global__ void k_att1(const float* __restrict__ att_s, const float* __restrict__ att_d) {
    int gw = (blockIdx.x * blockDim.x + threadIdx.x) >> 5;
    int lane = threadIdx.x & 31;
    if (gw >= NN) return;
    float2 v = *(const float2*)&g_xw[(size_t)gw * 64 + lane * 2];
    float2 s = *(const float2*)&att_s[lane * 2];
    float2 d = *(const float2*)&att_d[lane * 2];
    float ps = v.x * s.x + v.y * s.y;
    float pd = v.x * d.x + v.y * d.y;
#pragma unroll
    for (int o = 16; o > 0; o >>= 1) {
        ps += __shfl_xor_sync(0xffffffffu, ps, o);
        pd += __shfl_xor_sync(0xffffffffu, pd, o);
    }
    if (lane == 0) { g_as[gw] = ps; g_ad[gw] = pd; }
}

// ================= per-edge scores, CSR-ordered =================
template <int H>
__global__ void k_score(const int* __restrict__ ei) {
    for (int j = blockIdx.x * blockDim.x + threadIdx.x; j < ET;
         j += gridDim.x * blockDim.x) {
        int e = g_eid[j];
        int s = edge_src(ei, e);
        int d = edge_dst(ei, e);
        if (H == 2) {
            float2 a = *(const float2*)&g_as[(size_t)s * 2];
            float2 b = *(const float2*)&g_ad[(size_t)d * 2];
            *(float2*)&g_esc[(size_t)j * 2] =
                make_float2(lrelu(a.x + b.x), lrelu(a.y + b.y));
        } else {
            g_esc[j] = lrelu(g_as[s] + g_ad[d]);
        }
    }
}

// ================= per-node softmax + aggregation =================
template <int H, int SEL>
__global__ void k_agg(const int* __restrict__ ei, const float* __restrict__ bias,
                      float* __restrict__ alpha_out) {
    int node = (blockIdx.x * blockDim.x + threadIdx.x) >> 5;
    int lane = threadIdx.x & 31;
    if (node >= NN) return;
    const int s0 = g_off[node];
    const int s1 = g_off[node + 1];

    // pass 1: segment max (coalesced streaming read of g_esc)
    float m0 = -INFINITY, m1 = -INFINITY;
    for (int j = s0 + lane; j < s1; j += 32) {
        if (H == 2) {
            float2 t = *(const float2*)&g_esc[(size_t)j * 2];
            m0 = fmaxf(m0, t.x); m1 = fmaxf(m1, t.y);
        } else {
            m0 = fmaxf(m0, g_esc[j]);
        }
    }
#pragma unroll
    for (int o = 16; o > 0; o >>= 1) {
        m0 = fmaxf(m0, __shfl_xor_sync(0xffffffffu, m0, o));
        if (H == 2) m1 = fmaxf(m1, __shfl_xor_sync(0xffffffffu, m1, o));
    }

    // pass 2: segment sum of exp
    float sum0 = 0.f, sum1 = 0.f;
    for (int j = s0 + lane; j < s1; j += 32) {
        if (H == 2) {
            float2 t = *(const float2*)&g_esc[(size_t)j * 2];
            sum0 += expf(t.x - m0); sum1 += expf(t.y - m1);
        } else {
            sum0 += expf(g_esc[j] - m0);
        }
    }
#pragma unroll
    for (int o = 16; o > 0; o >>= 1) {
        sum0 += __shfl_xor_sync(0xffffffffu, sum0, o);
        if (H == 2) sum1 += __shfl_xor_sync(0xffffffffu, sum1, o);
    }
    const float inv0 = 1.f / (sum0 + 1e-16f);
    const float inv1 = (H == 2) ? 1.f / (sum1 + 1e-16f) : 0.f;

    // pass 3: weighted aggregation (warp-wide gather per edge)
    float acc0 = 0.f, acc1 = 0.f, acc2 = 0.f, acc3 = 0.f;
    for (int j = s0; j < s1; j++) {
        int e = g_eid[j];  // uniform broadcast load
        float a0, a1 = 0.f;
        if (H == 2) {
            float2 t = *(const float2*)&g_esc[(size_t)j * 2];  // broadcast
            a0 = expf(t.x - m0) * inv0;
            a1 = expf(t.y - m1) * inv1;
        } else {
            a0 = expf(g_esc[j] - m0) * inv0;
        }
        if (lane == 0) {
            if (H == 2) *(float2*)&alpha_out[(size_t)e * 2] = make_float2(a0, a1);
            else alpha_out[e] = a0;
        }
        int src = edge_src(ei, e);  // uniform broadcast load
        if (H == 2) {
            float4 v = *(const float4*)&g_xw[(size_t)src * 128 + lane * 4];
            float a = (lane < 16) ? a0 : a1;
            acc0 += a * v.x; acc1 += a * v.y; acc2 += a * v.z; acc3 += a * v.w;
        } else {
            float2 v = *(const float2*)&g_xw[(size_t)src * 64 + lane * 2];
            acc0 += a0 * v.x; acc1 += a0 * v.y;
        }
    }

    if (H == 2) {
        float4 b = *(const float4*)&bias[lane * 4];
        float* out = (SEL == 1) ? g_x1 : g_x2;
        *(float4*)&out[(size_t)node * 128 + lane * 4] =
            make_float4(acc0 + b.x, acc1 + b.y, acc2 + b.z, acc3 + b.w);
    } else {
        float2 b = *(const float2*)&bias[lane * 2];
        *(float2*)&g_x3[(size_t)node * 64 + lane * 2] =
            make_float2(acc0 + b.x, acc1 + b.y);
    }
}

// ================= final combine + output slices =================
__global__ void k_final(const float* __restrict__ Ei, const float* __restrict__ Eu,
                        const float* __restrict__ Ef, float* __restrict__ out) {
    int t = blockIdx.x * blockDim.x + threadIdx.x;
    if (t >= NN * 16) return;
    int n = t >> 4;
    int dq = (t & 15) * 4;
    const float* x0p = (n < NI) ? (Ei + (size_t)n * 64)
                     : (n < NI + NU) ? (Eu + (size_t)(n - NI) * 64)
                                     : (Ef + (size_t)(n - NI - NU) * 64);
    float4 x0 = *(const float4*)(x0p + dq);
    float4 a = *(const float4*)&g_x1[(size_t)n * 128 + dq];
    float4 b = *(const float4*)&g_x1[(size_t)n * 128 + 64 + dq];
    float4 c = *(const float4*)&g_x2[(size_t)n * 128 + dq];
    float4 d = *(const float4*)&g_x2[(size_t)n * 128 + 64 + dq];
    float4 x3 = *(const float4*)&g_x3[(size_t)n * 64 + dq];
    float4 f;
    f.x = (x0.x + 0.5f * (a.x + b.x) + 0.5f * (c.x + d.x) + x3.x) * 0.25f;
    f.y = (x0.y + 0.5f * (a.y + b.y) + 0.5f * (c.y + d.y) + x3.y) * 0.25f;
    f.z = (x0.z + 0.5f * (a.z + b.z) + 0.5f * (c.z + d.z) + x3.z) * 0.25f;
    f.w = (x0.w + 0.5f * (a.w + b.w) + 0.5f * (c.w + d.w) + x3.w) * 0.25f;
    *(float4*)&out[OFF_FINAL + (size_t)n * 64 + dq] = f;
    size_t so = (n < NI) ? (OFF_ITEM + (size_t)n * 64)
              : (n < NI + NU) ? (OFF_USER + (size_t)(n - NI) * 64)
                              : (OFF_FET + (size_t)(n - NI - NU) * 64);
    *(float4*)&out[so + dq] = f;
}

// ================= host launcher =================
extern "C" void kernel_launch(void* const* d_in, const int* in_sizes, int n_in,
                              void* d_out, int out_size) {
    const int*   ei   = (const int*)d_in[0];
    const float* embi = (const float*)d_in[1];
    const float* embu = (const float*)d_in[2];
    const float* embf = (const float*)d_in[3];
    const float* W1   = (const float*)d_in[4];
    const float* as1  = (const float*)d_in[5];
    const float* ad1  = (const float*)d_in[6];
    const float* b1   = (const float*)d_in[7];
    const float* W2   = (const float*)d_in[8];
    const float* as2  = (const float*)d_in[9];
    const float* ad2  = (const float*)d_in[10];
    const float* b2   = (const float*)d_in[11];
    const float* W3   = (const float*)d_in[12];
    const float* as3  = (const float*)d_in[13];
    const float* ad3  = (const float*)d_in[14];
    const float* b3   = (const float*)d_in[15];
    float* out = (float*)d_out;

    const int SCAN_BLOCKS = (NN + 1023) / 1024;  // 98
    const int GEMM_GRID = (NN + 127) / 128;      // 782
    const int WARP_GRID = (NN + 7) / 8;          // 12500 blocks of 8 warps

    // ---- CSR build head + layer-1 GEMM ordered so ncu (-s 5 -c 1) lands on gemm ----
    k_zero_cnt<<<(NN + 255) / 256, 256>>>();                 // 1
    k_count<<<2048, 256>>>(ei);                              // 2
    k_scan1<<<SCAN_BLOCKS, 1024>>>();                        // 3
    k_scan2<<<1, 128>>>(SCAN_BLOCKS);                        // 4
    k_scan3<<<SCAN_BLOCKS, 1024>>>();                        // 5 (+cursor init)
    k_gemm<64, 128, 0><<<GEMM_GRID, 256>>>(embi, embu, embf, W1);  // 6 <- profiled
    k_scatter<<<2048, 256>>>(ei);                            // 7

    // ---- layer 1 ----
    k_att2<<<WARP_GRID, 256>>>(as1, ad1);
    k_score<2><<<2048, 256>>>(ei);
    k_agg<2, 1><<<WARP_GRID, 256>>>(ei, b1, out + OFF_A1);

    // ---- layer 2 ----
    k_gemm<128, 128, 1><<<GEMM_GRID, 256>>>(embi, embu, embf, W2);
    k_att2<<<WARP_GRID, 256>>>(as2, ad2);
    k_score<2><<<2048, 256>>>(ei);
    k_agg<2, 2><<<WARP_GRID, 256>>>(ei, b2, out + OFF_A2);

    // ---- layer 3 ----
    k_gemm<128, 64, 2><<<GEMM_GRID, 256>>>(embi, embu, embf, W3);
    k_att1<<<WARP_GRID, 256>>>(as3, ad3);
    k_score<1><<<2048, 256>>>(ei);
    k_agg<1, 3><<<WARP_GRID, 256>>>(ei, b3, out + OFF_A3);

    // ---- final combine ----
    k_final<<<(NN * 16 + 255) / 256, 256>>>(embi, embu, embf, out);
}

// round 4
// speedup vs baseline: 1.1384x; 1.1149x over previous
#include <cuda_runtime.h>
#include <cstdint>

#define NI 40000
#define NU 30000
#define NF 30000
#define NN 100000
#define EE 1200000
#define ET (EE + NN)
#define NEG 0.2f

// ---- output layout (tuple order, flattened) ----
static const size_t OFF_ITEM  = 0;
static const size_t OFF_USER  = OFF_ITEM + (size_t)NI * 64;
static const size_t OFF_FET   = OFF_USER + (size_t)NU * 64;
static const size_t OFF_FINAL = OFF_FET  + (size_t)NF * 64;
static const size_t OFF_A1    = OFF_FINAL + (size_t)NN * 64;
static const size_t OFF_A2    = OFF_A1 + (size_t)ET * 2;
static const size_t OFF_A3    = OFF_A2 + (size_t)ET * 2;

// ---- scratch (device globals; no allocation allowed) ----
__device__ float g_xw[(size_t)NN * 128];
__device__ float g_x1[(size_t)NN * 128];
__device__ float g_x2[(size_t)NN * 128];
__device__ float g_x3[(size_t)NN * 64];
__device__ float g_as[(size_t)NN * 2];
__device__ float g_ad[(size_t)NN * 2];
__device__ float g_esc[(size_t)ET * 2];   // CSR-ordered edge scores
__device__ float g_alf[(size_t)ET * 2];   // CSR-ordered alphas
__device__ float g_mi[(size_t)NN * 4];    // per-node {m0,m1,inv0,inv1}
__device__ int   g_cnt[NN];
__device__ int   g_off[NN + 1];
__device__ int   g_cur[NN];
__device__ int   g_eid[ET];
__device__ int   g_srcid[ET];
__device__ int   g_dstid[ET];
__device__ int   g_bsum[128];

__device__ __forceinline__ int edge_src(const int* ei, int e) {
    return (e < EE) ? ei[e] : (e - EE);
}
__device__ __forceinline__ int edge_dst(const int* ei, int e) {
    return (e < EE) ? ei[EE + e] : (e - EE);
}
__device__ __forceinline__ float lrelu(float x) { return x > 0.f ? x : NEG * x; }

// ---- tf32 helpers (baseline PTX, no sm_103a-gated features) ----
__device__ __forceinline__ uint32_t f2tf32(float x) {
    uint32_t u;
    asm("cvt.rna.tf32.f32 %0, %1;" : "=r"(u) : "f"(x));
    return u;
}
__device__ __forceinline__ void hilo(float v, uint32_t& h, uint32_t& l) {
    h = f2tf32(v);
    l = f2tf32(v - __uint_as_float(h));
}
__device__ __forceinline__ void mma8(float* d, const uint32_t* a, const uint32_t* b) {
    asm volatile(
        "mma.sync.aligned.m16n8k8.row.col.f32.tf32.tf32.f32 "
        "{%0,%1,%2,%3}, {%4,%5,%6,%7}, {%8,%9}, {%0,%1,%2,%3};"
        : "+f"(d[0]), "+f"(d[1]), "+f"(d[2]), "+f"(d[3])
        : "r"(a[0]), "r"(a[1]), "r"(a[2]), "r"(a[3]), "r"(b[0]), "r"(b[1]));
}

// ================= CSR build =================
__global__ void k_zero_cnt() {
    int i = blockIdx.x * blockDim.x + threadIdx.x;
    if (i < NN) g_cnt[i] = 0;
}

__global__ void k_count(const int* __restrict__ ei) {
    for (int e = blockIdx.x * blockDim.x + threadIdx.x; e < ET;
         e += gridDim.x * blockDim.x)
        atomicAdd(&g_cnt[edge_dst(ei, e)], 1);
}

__global__ void k_scan1() {
    __shared__ int sh[1024];
    int i = blockIdx.x * 1024 + threadIdx.x;
    int v = (i < NN) ? g_cnt[i] : 0;
    sh[threadIdx.x] = v;
    __syncthreads();
    for (int o = 1; o < 1024; o <<= 1) {
        int t = (threadIdx.x >= (unsigned)o) ? sh[threadIdx.x - o] : 0;
        __syncthreads();
        sh[threadIdx.x] += t;
        __syncthreads();
    }
    if (i < NN) g_off[i + 1] = sh[threadIdx.x];
    if (threadIdx.x == 1023) g_bsum[blockIdx.x] = sh[1023];
}

__global__ void k_scan2(int nb) {
    __shared__ int sh[128];
    int v = ((int)threadIdx.x < nb) ? g_bsum[threadIdx.x] : 0;
    sh[threadIdx.x] = v;
    __syncthreads();
    for (int o = 1; o < 128; o <<= 1) {
        int t = (threadIdx.x >= (unsigned)o) ? sh[threadIdx.x - o] : 0;
        __syncthreads();
        sh[threadIdx.x] += t;
        __syncthreads();
    }
    if ((int)threadIdx.x < nb) g_bsum[threadIdx.x] = sh[threadIdx.x] - v;
}

__global__ void k_scan3() {
    int i = blockIdx.x * 1024 + threadIdx.x;
    if (i < NN) {
        int v = g_off[i + 1] + g_bsum[blockIdx.x];
        g_off[i + 1] = v;
        if (i + 1 < NN) g_cur[i + 1] = v;
    }
    if (i == 0) { g_off[0] = 0; g_cur[0] = 0; }
}

__global__ void k_scatter(const int* __restrict__ ei) {
    for (int e = blockIdx.x * blockDim.x + threadIdx.x; e < ET;
         e += gridDim.x * blockDim.x) {
        int s = edge_src(ei, e);
        int d = edge_dst(ei, e);
        int pos = atomicAdd(&g_cur[d], 1);
        g_eid[pos] = e;
        g_srcid[pos] = s;
        g_dstid[pos] = d;
    }
}

// ================= mma.sync tf32 GEMM (3xTF32 fp32 emulation) =================
// D[128 x NC] per CTA = act(A)[128 x KD] @ W[KD x NC].
// 8 warps: warp_m = wid&3 (32 rows), warp_n = wid>>2 (NC/2 cols).
template <int KD, int NC, int AMODE>
__global__ void __launch_bounds__(256)
k_gemm_mma(const float* __restrict__ Ei, const float* __restrict__ Eu,
           const float* __restrict__ Ef, const float* __restrict__ W) {
    constexpr int BM = 128, KC = 32;
    constexpr int KCP = KC + 4;          // 36: A row stride (bank-conflict-free)
    constexpr int NCP = NC + 4;          // B row stride
    constexpr int WN = NC / 2;           // per-warp N extent
    constexpr int AN = WN / 8;           // N atoms per warp (8 or 4)
    constexpr int A_ELEM = BM * KCP;
    constexpr int B_ELEM = KC * NCP;

    extern __shared__ float sm[];
    float* As_h = sm;
    float* As_l = As_h + A_ELEM;
    float* Bs_h = As_l + A_ELEM;
    float* Bs_l = Bs_h + B_ELEM;

    const int tid = threadIdx.x;
    const int lane = tid & 31;
    const int wid = tid >> 5;
    const int warp_m = wid & 3;
    const int warp_n = wid >> 2;
    const int quad = lane >> 2;
    const int qt = lane & 3;
    const int r0 = blockIdx.x * BM;

    float acc[2][AN][4];
#pragma unroll
    for (int i = 0; i < 2; i++)
#pragma unroll
        for (int j = 0; j < AN; j++)
#pragma unroll
            for (int c = 0; c < 4; c++) acc[i][j][c] = 0.f;

    for (int k0 = 0; k0 < KD; k0 += KC) {
        // ---- A tile: BM x KC, hi/lo ----
#pragma unroll
        for (int it = 0; it < (BM * KC / 4) / 256; it++) {
            int idx = tid + it * 256;
            int row = idx >> 3;            // KC/4 = 8 float4 per row
            int kq = (idx & 7) * 4;
            float4 v = make_float4(0.f, 0.f, 0.f, 0.f);
            int gr = r0 + row;
            if (gr < NN) {
                const float* ap;
                if (AMODE == 0) {
                    ap = (gr < NI) ? (Ei + (size_t)gr * 64)
                        : (gr < NI + NU) ? (Eu + (size_t)(gr - NI) * 64)
                                         : (Ef + (size_t)(gr - NI - NU) * 64);
                } else {
                    ap = ((AMODE == 1) ? g_x1 : g_x2) + (size_t)gr * KD;
                }
                v = *(const float4*)(ap + k0 + kq);
                if (AMODE != 0) {
                    v.x = fmaxf(v.x, 0.f); v.y = fmaxf(v.y, 0.f);
                    v.z = fmaxf(v.z, 0.f); v.w = fmaxf(v.w, 0.f);
                }
            }
            uint32_t h0, l0, h1, l1, h2, l2, h3, l3;
            hilo(v.x, h0, l0); hilo(v.y, h1, l1);
            hilo(v.z, h2, l2); hilo(v.w, h3, l3);
            float* ph = As_h + row * KCP + kq;
            float* pl = As_l + row * KCP + kq;
            *(float4*)ph = make_float4(__uint_as_float(h0), __uint_as_float(h1),
                                       __uint_as_float(h2), __uint_as_float(h3));
            *(float4*)pl = make_float4(__uint_as_float(l0), __uint_as_float(l1),
                                       __uint_as_float(l2), __uint_as_float(l3));
        }
        // ---- B tile: KC x NC, hi/lo ----
#pragma unroll
        for (int it = 0; it < (KC * NC / 4) / 256; it++) {
            int idx = tid + it * 256;
            int kk = idx / (NC / 4);
            int nq = (idx % (NC / 4)) * 4;
            float4 v = *(const float4*)&W[(size_t)(k0 + kk) * NC + nq];
            uint32_t h0, l0, h1, l1, h2, l2, h3, l3;
            hilo(v.x, h0, l0); hilo(v.y, h1, l1);
            hilo(v.z, h2, l2); hilo(v.w, h3, l3);
            float* ph = Bs_h + kk * NCP + nq;
            float* pl = Bs_l + kk * NCP + nq;
            *(float4*)ph = make_float4(__uint_as_float(h0), __uint_as_float(h1),
                                       __uint_as_float(h2), __uint_as_float(h3));
            *(float4*)pl = make_float4(__uint_as_float(l0), __uint_as_float(l1),
                                       __uint_as_float(l2), __uint_as_float(l3));
        }
        __syncthreads();

        // ---- compute: 4 k8 steps per chunk ----
#pragma unroll
        for (int kc = 0; kc < KC / 8; kc++) {
            const int k8 = kc * 8;
            // B fragments for this k8 (shared across both atom_m)
            uint32_t bh[AN][2], bl[AN][2];
#pragma unroll
            for (int j = 0; j < AN; j++) {
                int n = warp_n * WN + j * 8 + quad;
                bh[j][0] = __float_as_uint(Bs_h[(k8 + qt) * NCP + n]);
                bh[j][1] = __float_as_uint(Bs_h[(k8 + qt + 4) * NCP + n]);
                bl[j][0] = __float_as_uint(Bs_l[(k8 + qt) * NCP + n]);
                bl[j][1] = __float_as_uint(Bs_l[(k8 + qt + 4) * NCP + n]);
            }
#pragma unroll
            for (int i = 0; i < 2; i++) {
                int row = warp_m * 32 + i * 16 + quad;
                uint32_t ah[4], al[4];
                ah[0] = __float_as_uint(As_h[row * KCP + k8 + qt]);
                ah[1] = __float_as_uint(As_h[(row + 8) * KCP + k8 + qt]);
                ah[2] = __float_as_uint(As_h[row * KCP + k8 + qt + 4]);
                ah[3] = __float_as_uint(As_h[(row + 8) * KCP + k8 + qt + 4]);
                al[0] = __float_as_uint(As_l[row * KCP + k8 + qt]);
                al[1] = __float_as_uint(As_l[(row + 8) * KCP + k8 + qt]);
                al[2] = __float_as_uint(As_l[row * KCP + k8 + qt + 4]);
                al[3] = __float_as_uint(As_l[(row + 8) * KCP + k8 + qt + 4]);
#pragma unroll
                for (int j = 0; j < AN; j++) {
                    mma8(acc[i][j], ah, bh[j]);   // hi*hi
                    mma8(acc[i][j], ah, bl[j]);   // hi*lo
                    mma8(acc[i][j], al, bh[j]);   // lo*hi
                }
            }
        }
        __syncthreads();
    }

    // ---- epilogue ----
#pragma unroll
    for (int i = 0; i < 2; i++) {
        int row = r0 + warp_m * 32 + i * 16 + quad;
#pragma unroll
        for (int j = 0; j < AN; j++) {
            int col = warp_n * WN + j * 8 + qt * 2;
            if (row < NN)
                *(float2*)&g_xw[(size_t)row * NC + col] =
                    make_float2(acc[i][j][0], acc[i][j][1]);
            if (row + 8 < NN)
                *(float2*)&g_xw[(size_t)(row + 8) * NC + col] =
                    make_float2(acc[i][j][2], acc[i][j][3]);
        }
    }
}

// ================= attention scores a_src/a_dst =================
__global__ void k_att2(const float* __restrict__ att_s, const float* __restrict__ att_d) {
    int gw = (blockIdx.x * blockDim.x + threadIdx.x) >> 5;
    int lane = threadIdx.x & 31;
    if (gw >= NN) return;
    float4 v = *(const float4*)&g_xw[(size_t)gw * 128 + lane * 4];
    float4 s = *(const float4*)&att_s[lane * 4];
    float4 d = *(const float4*)&att_d[lane * 4];
    float ps = v.x * s.x + v.y * s.y + v.z * s.z + v.w * s.w;
    float pd = v.x * d.x + v.y * d.y + v.z * d.z + v.w * d.w;
#pragma unroll
    for (int o = 8; o > 0; o >>= 1) {
        ps += __shfl_xor_sync(0xffffffffu, ps, o, 16);
        pd += __shfl_xor_sync(0xffffffffu, pd, o, 16);
    }
    if ((lane & 15) == 0) {
        g_as[gw * 2 + (lane >> 4)] = ps;
        g_ad[gw * 2 + (lane >> 4)] = pd;
    }
}

__global__ void k_att1(const float* __restrict__ att_s, const float* __restrict__ att_d) {
    int gw = (blockIdx.x * blockDim.x + threadIdx.x) >> 5;
    int lane = threadIdx.x & 31;
    if (gw >= NN) return;
    float2 v = *(const float2*)&g_xw[(size_t)gw * 64 + lane * 2];
    float2 s = *(const float2*)&att_s[lane * 2];
    float2 d = *(const float2*)&att_d[lane * 2];
    float ps = v.x * s.x + v.y * s.y;
    float pd = v.x * d.x + v.y * d.y;
#pragma unroll
    for (int o = 16; o > 0; o >>= 1) {
        ps += __shfl_xor_sync(0xffffffffu, ps, o);
        pd += __shfl_xor_sync(0xffffffffu, pd, o);
    }
    if (lane == 0) { g_as[gw] = ps; g_ad[gw] = pd; }
}

// ================= per-edge scores (CSR order) =================
template <int H>
__global__ void k_score() {
    for (int j = blockIdx.x * blockDim.x + threadIdx.x; j < ET;
         j += gridDim.x * blockDim.x) {
        int s = g_srcid[j];
        int d = g_dstid[j];
        if (H == 2) {
            float2 a = *(const float2*)&g_as[(size_t)s * 2];
            float2 b = *(const float2*)&g_ad[(size_t)d * 2];
            *(float2*)&g_esc[(size_t)j * 2] =
                make_float2(lrelu(a.x + b.x), lrelu(a.y + b.y));
        } else {
            g_esc[j] = lrelu(g_as[s] + g_ad[d]);
        }
    }
}

// ================= per-node softmax stats (m, 1/sum) =================
template <int H>
__global__ void k_softmax() {
    int node = (blockIdx.x * blockDim.x + threadIdx.x) >> 5;
    int lane = threadIdx.x & 31;
    if (node >= NN) return;
    const int s0 = g_off[node], s1 = g_off[node + 1];
    float m0 = -INFINITY, m1 = -INFINITY;
    for (int j = s0 + lane; j < s1; j += 32) {
        if (H == 2) {
            float2 t = *(const float2*)&g_esc[(size_t)j * 2];
            m0 = fmaxf(m0, t.x); m1 = fmaxf(m1, t.y);
        } else m0 = fmaxf(m0, g_esc[j]);
    }
#pragma unroll
    for (int o = 16; o > 0; o >>= 1) {
        m0 = fmaxf(m0, __shfl_xor_sync(0xffffffffu, m0, o));
        if (H == 2) m1 = fmaxf(m1, __shfl_xor_sync(0xffffffffu, m1, o));
    }
    float sum0 = 0.f, sum1 = 0.f;
    for (int j = s0 + lane; j < s1; j += 32) {
        if (H == 2) {
            float2 t = *(const float2*)&g_esc[(size_t)j * 2];
            sum0 += expf(t.x - m0); sum1 += expf(t.y - m1);
        } else sum0 += expf(g_esc[j] - m0);
    }
#pragma unroll
    for (int o = 16; o > 0; o >>= 1) {
        sum0 += __shfl_xor_sync(0xffffffffu, sum0, o);
        if (H == 2) sum1 += __shfl_xor_sync(0xffffffffu, sum1, o);
    }
    if (lane == 0) {
        if (H == 2)
            *(float4*)&g_mi[(size_t)node * 4] =
                make_float4(m0, m1, 1.f / (sum0 + 1e-16f), 1.f / (sum1 + 1e-16f));
        else
            *(float2*)&g_mi[(size_t)node * 2] = make_float2(m0, 1.f / (sum0 + 1e-16f));
    }
}

// ================= per-edge alpha (CSR order + scattered output) =================
template <int H>
__global__ void k_alpha(float* __restrict__ alpha_out) {
    for (int j = blockIdx.x * blockDim.x + threadIdx.x; j < ET;
         j += gridDim.x * blockDim.x) {
        int d = g_dstid[j];
        int e = g_eid[j];
        if (H == 2) {
            float4 mi = *(const float4*)&g_mi[(size_t)d * 4];
            float2 t = *(const float2*)&g_esc[(size_t)j * 2];
            float2 a = make_float2(expf(t.x - mi.x) * mi.z, expf(t.y - mi.y) * mi.w);
            *(float2*)&g_alf[(size_t)j * 2] = a;
            *(float2*)&alpha_out[(size_t)e * 2] = a;
        } else {
            float2 mi = *(const float2*)&g_mi[(size_t)d * 2];
            float a = expf(g_esc[j] - mi.x) * mi.y;
            g_alf[j] = a;
            alpha_out[e] = a;
        }
    }
}

// ================= per-node aggregation (shuffle-broadcast gather) =================
template <int H, int SEL>
__global__ void k_agg3(const float* __restrict__ bias) {
    int node = (blockIdx.x * blockDim.x + threadIdx.x) >> 5;
    int lane = threadIdx.x & 31;
    if (node >= NN) return;
    const int s0 = g_off[node], s1 = g_off[node + 1];

    float acc0 = 0.f, acc1 = 0.f, acc2 = 0.f, acc3 = 0.f;
    for (int base = s0; base < s1; base += 32) {
        int jj = base + lane;
        int srcv = 0;
        float a0v = 0.f, a1v = 0.f;
        if (jj < s1) {
            srcv = g_srcid[jj];
            if (H == 2) {
                float2 t = *(const float2*)&g_alf[(size_t)jj * 2];
                a0v = t.x; a1v = t.y;
            } else a0v = g_alf[jj];
        }
        int n = min(32, s1 - base);
        for (int t = 0; t < n; t++) {
            int src = __shfl_sync(0xffffffffu, srcv, t);
            float a0 = __shfl_sync(0xffffffffu, a0v, t);
            if (H == 2) {
                float a1 = __shfl_sync(0xffffffffu, a1v, t);
                float4 v = *(const float4*)&g_xw[(size_t)src * 128 + lane * 4];
                float a = (lane < 16) ? a0 : a1;
                acc0 += a * v.x; acc1 += a * v.y; acc2 += a * v.z; acc3 += a * v.w;
            } else {
                float2 v = *(const float2*)&g_xw[(size_t)src * 64 + lane * 2];
                acc0 += a0 * v.x; acc1 += a0 * v.y;
            }
        }
    }

    if (H == 2) {
        float4 b = *(const float4*)&bias[lane * 4];
        float* out = (SEL == 1) ? g_x1 : g_x2;
        *(float4*)&out[(size_t)node * 128 + lane * 4] =
            make_float4(acc0 + b.x, acc1 + b.y, acc2 + b.z, acc3 + b.w);
    } else {
        float2 b = *(const float2*)&bias[lane * 2];
        *(float2*)&g_x3[(size_t)node * 64 + lane * 2] =
            make_float2(acc0 + b.x, acc1 + b.y);
    }
}

// ================= final combine + output slices =================
__global__ void k_final(const float* __restrict__ Ei, const float* __restrict__ Eu,
                        const float* __restrict__ Ef, float* __restrict__ out) {
    int t = blockIdx.x * blockDim.x + threadIdx.x;
    if (t >= NN * 16) return;
    int n = t >> 4;
    int dq = (t & 15) * 4;
    const float* x0p = (n < NI) ? (Ei + (size_t)n * 64)
                     : (n < NI + NU) ? (Eu + (size_t)(n - NI) * 64)
                                     : (Ef + (size_t)(n - NI - NU) * 64);
    float4 x0 = *(const float4*)(x0p + dq);
    float4 a = *(const float4*)&g_x1[(size_t)n * 128 + dq];
    float4 b = *(const float4*)&g_x1[(size_t)n * 128 + 64 + dq];
    float4 c = *(const float4*)&g_x2[(size_t)n * 128 + dq];
    float4 d = *(const float4*)&g_x2[(size_t)n * 128 + 64 + dq];
    float4 x3 = *(const float4*)&g_x3[(size_t)n * 64 + dq];
    float4 f;
    f.x = (x0.x + 0.5f * (a.x + b.x) + 0.5f * (c.x + d.x) + x3.x) * 0.25f;
    f.y = (x0.y + 0.5f * (a.y + b.y) + 0.5f * (c.y + d.y) + x3.y) * 0.25f;
    f.z = (x0.z + 0.5f * (a.z + b.z) + 0.5f * (c.z + d.z) + x3.z) * 0.25f;
    f.w = (x0.w + 0.5f * (a.w + b.w) + 0.5f * (c.w + d.w) + x3.w) * 0.25f;
    *(float4*)&out[OFF_FINAL + (size_t)n * 64 + dq] = f;
    size_t so = (n < NI) ? (OFF_ITEM + (size_t)n * 64)
              : (n < NI + NU) ? (OFF_USER + (size_t)(n - NI) * 64)
                              : (OFF_FET + (size_t)(n - NI - NU) * 64);
    *(float4*)&out[so + dq] = f;
}

// ================= host launcher =================
extern "C" void kernel_launch(void* const* d_in, const int* in_sizes, int n_in,
                              void* d_out, int out_size) {
    const int*   ei   = (const int*)d_in[0];
    const float* embi = (const float*)d_in[1];
    const float* embu = (const float*)d_in[2];
    const float* embf = (const float*)d_in[3];
    const float* W1   = (const float*)d_in[4];
    const float* as1  = (const float*)d_in[5];
    const float* ad1  = (const float*)d_in[6];
    const float* b1   = (const float*)d_in[7];
    const float* W2   = (const float*)d_in[8];
    const float* as2  = (const float*)d_in[9];
    const float* ad2  = (const float*)d_in[10];
    const float* b2   = (const float*)d_in[11];
    const float* W3   = (const float*)d_in[12];
    const float* as3  = (const float*)d_in[13];
    const float* ad3  = (const float*)d_in[14];
    const float* b3   = (const float*)d_in[15];
    float* out = (float*)d_out;

    const int SCAN_BLOCKS = (NN + 1023) / 1024;  // 98
    const int GEMM_GRID = (NN + 127) / 128;      // 782
    const int WARP_GRID = (NN + 7) / 8;          // 12500

    // dynamic smem sizes (floats): A: 2*128*36, B: 2*32*(NC+4)
    const int SM_128 = (2 * 128 * 36 + 2 * 32 * 132) * 4;  // 70656
    const int SM_64  = (2 * 128 * 36 + 2 * 32 * 68) * 4;   // 54272
    cudaFuncSetAttribute(k_gemm_mma<64, 128, 0>,
                         cudaFuncAttributeMaxDynamicSharedMemorySize, SM_128);
    cudaFuncSetAttribute(k_gemm_mma<128, 128, 1>,
                         cudaFuncAttributeMaxDynamicSharedMemorySize, SM_128);
    cudaFuncSetAttribute(k_gemm_mma<128, 64, 2>,
                         cudaFuncAttributeMaxDynamicSharedMemorySize, SM_64);

    // my-launch #4 = layer-1 GEMM (ncu -s 5 -c 1 profiles absolute #6 = my #4)
    k_zero_cnt<<<(NN + 255) / 256, 256>>>();                               // 1
    k_count<<<2048, 256>>>(ei);                                            // 2
    k_scan1<<<SCAN_BLOCKS, 1024>>>();                                      // 3
    k_gemm_mma<64, 128, 0><<<GEMM_GRID, 256, SM_128>>>(embi, embu, embf, W1);  // 4
    k_scan2<<<1, 128>>>(SCAN_BLOCKS);                                      // 5
    k_scan3<<<SCAN_BLOCKS, 1024>>>();                                      // 6
    k_scatter<<<2048, 256>>>(ei);                                          // 7

    // ---- layer 1 ----
    k_att2<<<WARP_GRID, 256>>>(as1, ad1);
    k_score<2><<<2048, 256>>>();
    k_softmax<2><<<WARP_GRID, 256>>>();
    k_alpha<2><<<2048, 256>>>(out + OFF_A1);
    k_agg3<2, 1><<<WARP_GRID, 256>>>(b1);

    // ---- layer 2 ----
    k_gemm_mma<128, 128, 1><<<GEMM_GRID, 256, SM_128>>>(embi, embu, embf, W2);
    k_att2<<<WARP_GRID, 256>>>(as2, ad2);
    k_score<2><<<2048, 256>>>();
    k_softmax<2><<<WARP_GRID, 256>>>();
    k_alpha<2><<<2048, 256>>>(out + OFF_A2);
    k_agg3<2, 2><<<WARP_GRID, 256>>>(b2);

    // ---- layer 3 ----
    k_gemm_mma<128, 64, 2><<<GEMM_GRID, 256, SM_64>>>(embi, embu, embf, W3);
    k_att1<<<WARP_GRID, 256>>>(as3, ad3);
    k_score<1><<<2048, 256>>>();
    k_softmax<1><<<WARP_GRID, 256>>>();
    k_alpha<1><<<2048, 256>>>(out + OFF_A3);
    k_agg3<1, 3><<<WARP_GRID, 256>>>(b3);

    // ---- final combine ----
    k_final<<<(NN * 16 + 255) / 256, 256>>>(embi, embu, embf, out);
}